// round 1
// baseline (speedup 1.0000x reference)
#include <cuda_runtime.h>
#include <math.h>
#include <stdint.h>

// Problem constants
#define BB   8
#define SS   8192
#define DD   512
#define EE   16
#define DFFN 512
#define KCAP 1024            // S/E * CAPACITY
#define NTOK (BB*SS)         // 65536
#define NGRP (BB*EE)         // 128

// Scratch (static device allocations are the sanctioned workaround)
__device__ float g_aff [NGRP * SS];                      // [g][s] softmax affinity, 4MB
__device__ int   g_idx [NGRP * KCAP];                    // selected token ids
__device__ float g_gate[NGRP * KCAP];                    // gating probs
__device__ float g_h   [(size_t)NGRP * KCAP * DFFN];     // hidden acts, 256MB

// ---------------------------------------------------------------------------
// Kernel 1: router — logits = x @ gate_weight, softmax over experts,
// write affinity transposed to [b,e,s]. One warp per token.
// ---------------------------------------------------------------------------
__global__ __launch_bounds__(256) void router_kernel(
    const float* __restrict__ x, const float* __restrict__ gw)
{
    __shared__ float sgw[EE * DD];   // transposed: sgw[e*DD + d]
    for (int i = threadIdx.x; i < EE * DD; i += blockDim.x) {
        int e = i / DD, d = i - e * DD;
        sgw[i] = gw[d * EE + e];
    }
    __syncthreads();

    int warp = threadIdx.x >> 5, lane = threadIdx.x & 31;
    int t = blockIdx.x * 8 + warp;            // 8 warps per block
    const float* xr = x + (size_t)t * DD;

    float acc[EE];
#pragma unroll
    for (int e = 0; e < EE; e++) acc[e] = 0.f;

#pragma unroll
    for (int i = 0; i < DD / 32; i++) {
        int d = lane + 32 * i;
        float xv = xr[d];
#pragma unroll
        for (int e = 0; e < EE; e++)
            acc[e] = fmaf(xv, sgw[e * DD + d], acc[e]);
    }
    // butterfly reduce each expert sum across the warp
#pragma unroll
    for (int e = 0; e < EE; e++) {
#pragma unroll
        for (int o = 16; o > 0; o >>= 1)
            acc[e] += __shfl_xor_sync(0xffffffffu, acc[e], o);
    }
    // softmax over 16 experts (all lanes hold full vector)
    float m = acc[0];
#pragma unroll
    for (int e = 1; e < EE; e++) m = fmaxf(m, acc[e]);
    float s = 0.f;
#pragma unroll
    for (int e = 0; e < EE; e++) { acc[e] = expf(acc[e] - m); s += acc[e]; }
    float inv = 1.f / s;

    int b = t / SS, srow = t - b * SS;
    if (lane < EE) {
        g_aff[((size_t)(b * EE + lane)) * SS + srow] = acc[lane] * inv;
    }
}

// ---------------------------------------------------------------------------
// Kernel 2: exact top-KCAP per (b,e) via 4-pass radix select on float bits
// (all values positive -> bit pattern is order-preserving). Ties at the
// threshold are taken in increasing index order (matches jax.lax.top_k).
// One block per group.
// ---------------------------------------------------------------------------
__global__ __launch_bounds__(256) void topk_kernel()
{
    int g = blockIdx.x;
    const float* a = g_aff + (size_t)g * SS;
    int tid = threadIdx.x;

    __shared__ unsigned hist[256];
    __shared__ unsigned sPrefix, sMask, sRemain;

    if (tid == 0) { sPrefix = 0u; sMask = 0u; sRemain = KCAP; }
    __syncthreads();

    for (int pass = 3; pass >= 0; pass--) {
        for (int i = tid; i < 256; i += blockDim.x) hist[i] = 0u;
        __syncthreads();
        unsigned pfx = sPrefix, msk = sMask;
        int sh = pass * 8;
        for (int s = tid; s < SS; s += blockDim.x) {
            unsigned key = __float_as_uint(a[s]);
            if ((key & msk) == pfx)
                atomicAdd(&hist[(key >> sh) & 0xFFu], 1u);
        }
        __syncthreads();
        if (tid == 0) {
            unsigned need = sRemain, cum = 0;
            int d = 255;
            for (; d > 0; d--) {
                if (cum + hist[d] >= need) break;
                cum += hist[d];
            }
            sRemain = need - cum;
            sPrefix = pfx | ((unsigned)d << sh);
            sMask   = msk | (0xFFu << sh);
        }
        __syncthreads();
    }

    unsigned T = sPrefix;          // exact key of KCAP-th largest
    int kEq   = (int)sRemain;      // # of ==T elements to take (lowest idx first)
    int cntGt = KCAP - kEq;

    __shared__ unsigned gtCnt;
    __shared__ int eqBase;
    __shared__ int warpEq[8];
    if (tid == 0) { gtCnt = 0u; eqBase = 0; }
    __syncthreads();

    int lane = tid & 31, warp = tid >> 5;
    int*   oIdx  = g_idx  + g * KCAP;
    float* oGate = g_gate + g * KCAP;

    for (int c = 0; c < SS / 256; c++) {
        int s = c * 256 + tid;
        float v = a[s];
        unsigned key = __float_as_uint(v);
        bool isGt = key > T, isEq = key == T;

        if (isGt) {                       // order among >T irrelevant (set semantics)
            unsigned p = atomicAdd(&gtCnt, 1u);
            oIdx[p] = s; oGate[p] = v;
        }
        unsigned bal = __ballot_sync(0xffffffffu, isEq);
        if (lane == 0) warpEq[warp] = __popc(bal);
        __syncthreads();
        if (isEq) {
            int r = eqBase;
#pragma unroll
            for (int w = 0; w < 8; w++) if (w < warp) r += warpEq[w];
            r += __popc(bal & ((1u << lane) - 1u));
            if (r < kEq) { oIdx[cntGt + r] = s; oGate[cntGt + r] = v; }
        }
        __syncthreads();
        if (tid == 0) {
            int tot = 0;
#pragma unroll
            for (int w = 0; w < 8; w++) tot += warpEq[w];
            eqBase += tot;
        }
        __syncthreads();
    }
}

// ---------------------------------------------------------------------------
// Kernel 3: zero the output (it is poisoned before timing)
// ---------------------------------------------------------------------------
__global__ void zero_kernel(float4* __restrict__ out, int n4)
{
    int i = blockIdx.x * blockDim.x + threadIdx.x;
    if (i < n4) out[i] = make_float4(0.f, 0.f, 0.f, 0.f);
}

// ---------------------------------------------------------------------------
// SGEMM tiling parameters (shared by kernels 4 & 5)
// ---------------------------------------------------------------------------
#define BM 64
#define BN 64
#define BK 32
#define TM 4
#define TN 4

__device__ __forceinline__ float gelu_tanh(float v)
{
    float v3 = v * v * v;
    float t = tanhf(0.7978845608028654f * (v + 0.044715f * v3));
    return 0.5f * v * (1.f + t);
}

// ---------------------------------------------------------------------------
// Kernel 4: per-(b,e) GEMM1 with fused gather + bias + gelu.
//   h[g, m, :] = gelu( x[b, idx[g,m], :] @ w1[e] + b1[e] )
// ---------------------------------------------------------------------------
__global__ __launch_bounds__(256) void gemm1_kernel(
    const float* __restrict__ x, const float* __restrict__ w1,
    const float* __restrict__ b1)
{
    __shared__ float As[BK][BM + 1];
    __shared__ float Bs[BK][BN];
    __shared__ int rowIdx[BM];

    int g = blockIdx.z;
    int b = g >> 4, e = g & 15;
    int m0 = blockIdx.y * BM, n0 = blockIdx.x * BN;
    int tid = threadIdx.x;

    if (tid < BM) rowIdx[tid] = g_idx[g * KCAP + m0 + tid];
    __syncthreads();

    const float* A_base = x + (size_t)b * SS * DD;
    const float* B_base = w1 + (size_t)e * DD * DFFN + n0;

    float acc[TM][TN] = {};
    int la_k = tid & 31, la_m = tid >> 5;      // A-load mapping
    int lb_n = tid & 63, lb_k = tid >> 6;      // B-load mapping
    int ty = tid >> 4, tx = tid & 15;

    for (int k0 = 0; k0 < DD; k0 += BK) {
#pragma unroll
        for (int r = 0; r < BM / 8; r++) {
            int m = la_m + r * 8;
            As[la_k][m] = A_base[(size_t)rowIdx[m] * DD + k0 + la_k];
        }
#pragma unroll
        for (int r = 0; r < BK / 4; r++) {
            int k = lb_k + r * 4;
            Bs[k][lb_n] = B_base[(size_t)(k0 + k) * DFFN + lb_n];
        }
        __syncthreads();
#pragma unroll
        for (int kk = 0; kk < BK; kk++) {
            float af[TM];
#pragma unroll
            for (int i = 0; i < TM; i++) af[i] = As[kk][ty * TM + i];
            float4 bf4 = *reinterpret_cast<const float4*>(&Bs[kk][tx * TN]);
            float bf[TN] = {bf4.x, bf4.y, bf4.z, bf4.w};
#pragma unroll
            for (int i = 0; i < TM; i++)
#pragma unroll
                for (int j = 0; j < TN; j++)
                    acc[i][j] = fmaf(af[i], bf[j], acc[i][j]);
        }
        __syncthreads();
    }

    float* H = g_h + ((size_t)g * KCAP + m0) * DFFN + n0;
#pragma unroll
    for (int i = 0; i < TM; i++) {
        int m = ty * TM + i;
#pragma unroll
        for (int j = 0; j < TN; j++) {
            int n = tx * TN + j;
            float v = acc[i][j] + b1[e * DFFN + n0 + n];
            H[(size_t)m * DFFN + n] = gelu_tanh(v);
        }
    }
}

// ---------------------------------------------------------------------------
// Kernel 5: per-(b,e) GEMM2 with fused bias + gate weight + atomic scatter.
//   out[b, idx[g,m], :] += gate[g,m] * ( h[g,m,:] @ w2[e] + b2[e] )
// ---------------------------------------------------------------------------
__global__ __launch_bounds__(256) void gemm2_kernel(
    const float* __restrict__ w2, const float* __restrict__ b2,
    float* __restrict__ out)
{
    __shared__ float As[BK][BM + 1];
    __shared__ float Bs[BK][BN];
    __shared__ int rowIdx[BM];
    __shared__ float rowGate[BM];

    int g = blockIdx.z;
    int b = g >> 4, e = g & 15;
    int m0 = blockIdx.y * BM, n0 = blockIdx.x * BN;
    int tid = threadIdx.x;

    if (tid < BM) {
        rowIdx[tid]  = g_idx [g * KCAP + m0 + tid];
        rowGate[tid] = g_gate[g * KCAP + m0 + tid];
    }
    __syncthreads();

    const float* A_base = g_h + ((size_t)g * KCAP + m0) * DFFN;
    const float* B_base = w2 + (size_t)e * DFFN * DD + n0;

    float acc[TM][TN] = {};
    int la_k = tid & 31, la_m = tid >> 5;
    int lb_n = tid & 63, lb_k = tid >> 6;
    int ty = tid >> 4, tx = tid & 15;

    for (int k0 = 0; k0 < DFFN; k0 += BK) {
#pragma unroll
        for (int r = 0; r < BM / 8; r++) {
            int m = la_m + r * 8;
            As[la_k][m] = A_base[(size_t)m * DFFN + k0 + la_k];
        }
#pragma unroll
        for (int r = 0; r < BK / 4; r++) {
            int k = lb_k + r * 4;
            Bs[k][lb_n] = B_base[(size_t)(k0 + k) * DD + lb_n];
        }
        __syncthreads();
#pragma unroll
        for (int kk = 0; kk < BK; kk++) {
            float af[TM];
#pragma unroll
            for (int i = 0; i < TM; i++) af[i] = As[kk][ty * TM + i];
            float4 bf4 = *reinterpret_cast<const float4*>(&Bs[kk][tx * TN]);
            float bf[TN] = {bf4.x, bf4.y, bf4.z, bf4.w};
#pragma unroll
            for (int i = 0; i < TM; i++)
#pragma unroll
                for (int j = 0; j < TN; j++)
                    acc[i][j] = fmaf(af[i], bf[j], acc[i][j]);
        }
        __syncthreads();
    }

    float* outB = out + (size_t)b * SS * DD;
#pragma unroll
    for (int i = 0; i < TM; i++) {
        int m = ty * TM + i;
        int tok = rowIdx[m];
        float gate = rowGate[m];
        float* orow = outB + (size_t)tok * DD + n0;
#pragma unroll
        for (int j = 0; j < TN; j++) {
            int n = tx * TN + j;
            float v = (acc[i][j] + b2[e * DD + n0 + n]) * gate;
            atomicAdd(&orow[n], v);
        }
    }
}

// ---------------------------------------------------------------------------
extern "C" void kernel_launch(void* const* d_in, const int* in_sizes, int n_in,
                              void* d_out, int out_size)
{
    const float* x  = (const float*)d_in[0];
    const float* gw = (const float*)d_in[1];
    const float* w1 = (const float*)d_in[2];
    const float* b1 = (const float*)d_in[3];
    const float* w2 = (const float*)d_in[4];
    const float* b2 = (const float*)d_in[5];
    float* out = (float*)d_out;

    router_kernel<<<NTOK / 8, 256>>>(x, gw);
    topk_kernel<<<NGRP, 256>>>();

    int n4 = out_size / 4;   // out_size = 33554432 floats
    zero_kernel<<<(n4 + 255) / 256, 256>>>((float4*)out, n4);

    dim3 gblk(256);
    dim3 g1(DFFN / BN, KCAP / BM, NGRP);
    gemm1_kernel<<<g1, gblk>>>(x, w1, b1);

    dim3 g2(DD / BN, KCAP / BM, NGRP);
    gemm2_kernel<<<g2, gblk>>>(w2, b2, out);
}

// round 2
// speedup vs baseline: 2.8382x; 2.8382x over previous
#include <cuda_runtime.h>
#include <math.h>
#include <stdint.h>

// Problem constants
#define BB   8
#define SS   8192
#define DD   512
#define EE   16
#define DFFN 512
#define KCAP 1024            // S/E * CAPACITY
#define NTOK (BB*SS)         // 65536
#define NGRP (BB*EE)         // 128

// Scratch
__device__ float g_aff [NGRP * SS];
__device__ int   g_idx [NGRP * KCAP];
__device__ float g_gate[NGRP * KCAP];
__device__ float g_h   [(size_t)NGRP * KCAP * DFFN];     // 256MB

// ---------------------------------------------------------------------------
// Kernel 1: router (unchanged — passed with exact selection)
// ---------------------------------------------------------------------------
__global__ __launch_bounds__(256) void router_kernel(
    const float* __restrict__ x, const float* __restrict__ gw)
{
    __shared__ float sgw[EE * DD];
    for (int i = threadIdx.x; i < EE * DD; i += blockDim.x) {
        int e = i / DD, d = i - e * DD;
        sgw[i] = gw[d * EE + e];
    }
    __syncthreads();

    int warp = threadIdx.x >> 5, lane = threadIdx.x & 31;
    int t = blockIdx.x * 8 + warp;
    const float* xr = x + (size_t)t * DD;

    float acc[EE];
#pragma unroll
    for (int e = 0; e < EE; e++) acc[e] = 0.f;
#pragma unroll
    for (int i = 0; i < DD / 32; i++) {
        int d = lane + 32 * i;
        float xv = xr[d];
#pragma unroll
        for (int e = 0; e < EE; e++)
            acc[e] = fmaf(xv, sgw[e * DD + d], acc[e]);
    }
#pragma unroll
    for (int e = 0; e < EE; e++) {
#pragma unroll
        for (int o = 16; o > 0; o >>= 1)
            acc[e] += __shfl_xor_sync(0xffffffffu, acc[e], o);
    }
    float m = acc[0];
#pragma unroll
    for (int e = 1; e < EE; e++) m = fmaxf(m, acc[e]);
    float s = 0.f;
#pragma unroll
    for (int e = 0; e < EE; e++) { acc[e] = expf(acc[e] - m); s += acc[e]; }
    float inv = 1.f / s;

    int b = t / SS, srow = t - b * SS;
    if (lane < EE)
        g_aff[((size_t)(b * EE + lane)) * SS + srow] = acc[lane] * inv;
}

// ---------------------------------------------------------------------------
// Kernel 2: exact radix-select top-KCAP (unchanged)
// ---------------------------------------------------------------------------
__global__ __launch_bounds__(256) void topk_kernel()
{
    int g = blockIdx.x;
    const float* a = g_aff + (size_t)g * SS;
    int tid = threadIdx.x;

    __shared__ unsigned hist[256];
    __shared__ unsigned sPrefix, sMask, sRemain;

    if (tid == 0) { sPrefix = 0u; sMask = 0u; sRemain = KCAP; }
    __syncthreads();

    for (int pass = 3; pass >= 0; pass--) {
        for (int i = tid; i < 256; i += blockDim.x) hist[i] = 0u;
        __syncthreads();
        unsigned pfx = sPrefix, msk = sMask;
        int sh = pass * 8;
        for (int s = tid; s < SS; s += blockDim.x) {
            unsigned key = __float_as_uint(a[s]);
            if ((key & msk) == pfx)
                atomicAdd(&hist[(key >> sh) & 0xFFu], 1u);
        }
        __syncthreads();
        if (tid == 0) {
            unsigned need = sRemain, cum = 0;
            int d = 255;
            for (; d > 0; d--) {
                if (cum + hist[d] >= need) break;
                cum += hist[d];
            }
            sRemain = need - cum;
            sPrefix = pfx | ((unsigned)d << sh);
            sMask   = msk | (0xFFu << sh);
        }
        __syncthreads();
    }

    unsigned T = sPrefix;
    int kEq   = (int)sRemain;
    int cntGt = KCAP - kEq;

    __shared__ unsigned gtCnt;
    __shared__ int eqBase;
    __shared__ int warpEq[8];
    if (tid == 0) { gtCnt = 0u; eqBase = 0; }
    __syncthreads();

    int lane = tid & 31, warp = tid >> 5;
    int*   oIdx  = g_idx  + g * KCAP;
    float* oGate = g_gate + g * KCAP;

    for (int c = 0; c < SS / 256; c++) {
        int s = c * 256 + tid;
        float v = a[s];
        unsigned key = __float_as_uint(v);
        bool isGt = key > T, isEq = key == T;

        if (isGt) {
            unsigned p = atomicAdd(&gtCnt, 1u);
            oIdx[p] = s; oGate[p] = v;
        }
        unsigned bal = __ballot_sync(0xffffffffu, isEq);
        if (lane == 0) warpEq[warp] = __popc(bal);
        __syncthreads();
        if (isEq) {
            int r = eqBase;
#pragma unroll
            for (int w = 0; w < 8; w++) if (w < warp) r += warpEq[w];
            r += __popc(bal & ((1u << lane) - 1u));
            if (r < kEq) { oIdx[cntGt + r] = s; oGate[cntGt + r] = v; }
        }
        __syncthreads();
        if (tid == 0) {
            int tot = 0;
#pragma unroll
            for (int w = 0; w < 8; w++) tot += warpEq[w];
            eqBase += tot;
        }
        __syncthreads();
    }
}

// ---------------------------------------------------------------------------
// Kernel 3: zero the output
// ---------------------------------------------------------------------------
__global__ void zero_kernel(float4* __restrict__ out, int n4)
{
    int i = blockIdx.x * blockDim.x + threadIdx.x;
    if (i < n4) out[i] = make_float4(0.f, 0.f, 0.f, 0.f);
}

// ---------------------------------------------------------------------------
// TF32 tensor-core GEMM machinery
// Block tile 128x128x16, 256 threads = 8 warps (4 m-warps x 2 n-warps),
// warp tile 32x64 via m16n8k8 (2 m-frags x 8 n-frags).
// ---------------------------------------------------------------------------
#define BM 128
#define BN 128
#define BKT 16
#define LDA 20      // BKT + 4 -> conflict-free A fragment loads
#define LDB 136     // BN + 8  -> conflict-free B fragment loads

__device__ __forceinline__ void cpa16(void* dst, const void* src)
{
    unsigned d = (unsigned)__cvta_generic_to_shared(dst);
    asm volatile("cp.async.cg.shared.global [%0], [%1], 16;\n" :: "r"(d), "l"(src));
}
#define CP_COMMIT() asm volatile("cp.async.commit_group;\n" ::: "memory")
#define CP_WAIT0()  asm volatile("cp.async.wait_group 0;\n" ::: "memory")

__device__ __forceinline__ unsigned f2tf32(float f)
{
    unsigned r;
    asm("cvt.rna.tf32.f32 %0, %1;" : "=r"(r) : "f"(f));
    return r;
}

__device__ __forceinline__ void mma_tf32(float* c, const unsigned* a, const unsigned* b)
{
    asm volatile(
        "mma.sync.aligned.m16n8k8.row.col.f32.tf32.tf32.f32 "
        "{%0,%1,%2,%3}, {%4,%5,%6,%7}, {%8,%9}, {%0,%1,%2,%3};\n"
        : "+f"(c[0]), "+f"(c[1]), "+f"(c[2]), "+f"(c[3])
        : "r"(a[0]), "r"(a[1]), "r"(a[2]), "r"(a[3]), "r"(b[0]), "r"(b[1]));
}

__device__ __forceinline__ float gelu_tanh(float v)
{
    float v3 = v * v * v;
    float t = tanhf(0.7978845608028654f * (v + 0.044715f * v3));
    return 0.5f * v * (1.f + t);
}

// Core compute over one smem stage
__device__ __forceinline__ void compute_stage(
    const float* __restrict__ A, const float* __restrict__ Bsh,
    int wm, int wn, int grp, int thr, float acc[2][8][4])
{
#pragma unroll
    for (int s = 0; s < 2; s++) {
        unsigned af[2][4], bf[8][2];
        int kc = s * 8 + thr;
#pragma unroll
        for (int f = 0; f < 2; f++) {
            int r0 = (wm * 32 + f * 16 + grp) * LDA;
            af[f][0] = f2tf32(A[r0 + kc]);
            af[f][1] = f2tf32(A[r0 + 8 * LDA + kc]);
            af[f][2] = f2tf32(A[r0 + kc + 4]);
            af[f][3] = f2tf32(A[r0 + 8 * LDA + kc + 4]);
        }
#pragma unroll
        for (int j = 0; j < 8; j++) {
            int col = wn * 64 + j * 8 + grp;
            bf[j][0] = f2tf32(Bsh[(s * 8 + thr) * LDB + col]);
            bf[j][1] = f2tf32(Bsh[(s * 8 + 4 + thr) * LDB + col]);
        }
#pragma unroll
        for (int f = 0; f < 2; f++)
#pragma unroll
            for (int j = 0; j < 8; j++)
                mma_tf32(acc[f][j], af[f], bf[j]);
    }
}

// ---------------------------------------------------------------------------
// Kernel 4: GEMM1 (TF32 TC) — fused gather + bias + gelu
// ---------------------------------------------------------------------------
__global__ __launch_bounds__(256) void gemm1_tc(
    const float* __restrict__ x, const float* __restrict__ w1,
    const float* __restrict__ b1)
{
    __shared__ float As[2][BM * LDA];
    __shared__ float Bs[2][BKT * LDB];

    int g = blockIdx.z;
    int b = g >> 4, e = g & 15;
    int m0 = blockIdx.y * BM, n0 = blockIdx.x * BN;
    int tid = threadIdx.x;

    // A loaders: gather rows by token index
    int mA0 = tid >> 2, kqA = (tid & 3) * 4;
    int mA1 = mA0 + 64;
    const float* xb = x + (size_t)b * SS * DD;
    int rA0 = g_idx[g * KCAP + m0 + mA0];
    int rA1 = g_idx[g * KCAP + m0 + mA1];
    const float* srcA0 = xb + (size_t)rA0 * DD + kqA;
    const float* srcA1 = xb + (size_t)rA1 * DD + kqA;

    // B loaders
    int kB0 = tid >> 5, nB = (tid & 31) * 4;
    int kB1 = kB0 + 8;
    const float* srcB = w1 + (size_t)e * DD * DFFN + n0 + nB;

    float acc[2][8][4] = {};

    int lane = tid & 31, warp = tid >> 5;
    int wm = warp >> 1, wn = warp & 1;
    int grp = lane >> 2, thr = lane & 3;

    // prefetch stage 0
    {
        cpa16(&As[0][mA0 * LDA + kqA], srcA0);
        cpa16(&As[0][mA1 * LDA + kqA], srcA1);
        cpa16(&Bs[0][kB0 * LDB + nB], srcB + (size_t)kB0 * DFFN);
        cpa16(&Bs[0][kB1 * LDB + nB], srcB + (size_t)kB1 * DFFN);
        CP_COMMIT();
    }

    const int KT = DD / BKT;   // 32
    for (int kt = 0; kt < KT; kt++) {
        CP_WAIT0();
        __syncthreads();
        if (kt + 1 < KT) {
            int st = (kt + 1) & 1;
            int k0 = (kt + 1) * BKT;
            cpa16(&As[st][mA0 * LDA + kqA], srcA0 + k0);
            cpa16(&As[st][mA1 * LDA + kqA], srcA1 + k0);
            cpa16(&Bs[st][kB0 * LDB + nB], srcB + (size_t)(k0 + kB0) * DFFN);
            cpa16(&Bs[st][kB1 * LDB + nB], srcB + (size_t)(k0 + kB1) * DFFN);
            CP_COMMIT();
        }
        compute_stage(As[kt & 1], Bs[kt & 1], wm, wn, grp, thr, acc);
    }

    // Epilogue: bias + gelu -> g_h
    float* Hrow = g_h + ((size_t)g * KCAP + m0) * DFFN + n0;
    const float* bias = b1 + e * DFFN + n0;
#pragma unroll
    for (int f = 0; f < 2; f++) {
        int mloc = wm * 32 + f * 16 + grp;
#pragma unroll
        for (int j = 0; j < 8; j++) {
            int nloc = wn * 64 + j * 8 + thr * 2;
            float bv0 = bias[nloc], bv1 = bias[nloc + 1];
            float2 v0 = make_float2(gelu_tanh(acc[f][j][0] + bv0),
                                    gelu_tanh(acc[f][j][1] + bv1));
            *(float2*)&Hrow[(size_t)mloc * DFFN + nloc] = v0;
            float2 v1 = make_float2(gelu_tanh(acc[f][j][2] + bv0),
                                    gelu_tanh(acc[f][j][3] + bv1));
            *(float2*)&Hrow[(size_t)(mloc + 8) * DFFN + nloc] = v1;
        }
    }
}

// ---------------------------------------------------------------------------
// Kernel 5: GEMM2 (TF32 TC) — fused bias + gate + atomic scatter
// ---------------------------------------------------------------------------
__global__ __launch_bounds__(256) void gemm2_tc(
    const float* __restrict__ w2, const float* __restrict__ b2,
    float* __restrict__ out)
{
    __shared__ float As[2][BM * LDA];
    __shared__ float Bs[2][BKT * LDB];

    int g = blockIdx.z;
    int b = g >> 4, e = g & 15;
    int m0 = blockIdx.y * BM, n0 = blockIdx.x * BN;
    int tid = threadIdx.x;

    int mA0 = tid >> 2, kqA = (tid & 3) * 4;
    int mA1 = mA0 + 64;
    const float* srcA0 = g_h + ((size_t)(g * KCAP + m0 + mA0)) * DFFN + kqA;
    const float* srcA1 = g_h + ((size_t)(g * KCAP + m0 + mA1)) * DFFN + kqA;

    int kB0 = tid >> 5, nB = (tid & 31) * 4;
    int kB1 = kB0 + 8;
    const float* srcB = w2 + (size_t)e * DFFN * DD + n0 + nB;

    float acc[2][8][4] = {};

    int lane = tid & 31, warp = tid >> 5;
    int wm = warp >> 1, wn = warp & 1;
    int grp = lane >> 2, thr = lane & 3;

    {
        cpa16(&As[0][mA0 * LDA + kqA], srcA0);
        cpa16(&As[0][mA1 * LDA + kqA], srcA1);
        cpa16(&Bs[0][kB0 * LDB + nB], srcB + (size_t)kB0 * DD);
        cpa16(&Bs[0][kB1 * LDB + nB], srcB + (size_t)kB1 * DD);
        CP_COMMIT();
    }

    const int KT = DFFN / BKT;   // 32
    for (int kt = 0; kt < KT; kt++) {
        CP_WAIT0();
        __syncthreads();
        if (kt + 1 < KT) {
            int st = (kt + 1) & 1;
            int k0 = (kt + 1) * BKT;
            cpa16(&As[st][mA0 * LDA + kqA], srcA0 + k0);
            cpa16(&As[st][mA1 * LDA + kqA], srcA1 + k0);
            cpa16(&Bs[st][kB0 * LDB + nB], srcB + (size_t)(k0 + kB0) * DD);
            cpa16(&Bs[st][kB1 * LDB + nB], srcB + (size_t)(k0 + kB1) * DD);
            CP_COMMIT();
        }
        compute_stage(As[kt & 1], Bs[kt & 1], wm, wn, grp, thr, acc);
    }

    // Epilogue: bias + gate weight + atomic scatter-add
    float* outB = out + (size_t)b * SS * DD;
    const float* bias = b2 + e * DD + n0;
#pragma unroll
    for (int f = 0; f < 2; f++) {
        int mloc = wm * 32 + f * 16 + grp;
        int gi = g * KCAP + m0 + mloc;
        int tok0 = g_idx[gi], tok1 = g_idx[gi + 8];
        float gt0 = g_gate[gi], gt1 = g_gate[gi + 8];
        float* o0 = outB + (size_t)tok0 * DD + n0;
        float* o1 = outB + (size_t)tok1 * DD + n0;
#pragma unroll
        for (int j = 0; j < 8; j++) {
            int nloc = wn * 64 + j * 8 + thr * 2;
            float bv0 = bias[nloc], bv1 = bias[nloc + 1];
            atomicAdd(&o0[nloc],     (acc[f][j][0] + bv0) * gt0);
            atomicAdd(&o0[nloc + 1], (acc[f][j][1] + bv1) * gt0);
            atomicAdd(&o1[nloc],     (acc[f][j][2] + bv0) * gt1);
            atomicAdd(&o1[nloc + 1], (acc[f][j][3] + bv1) * gt1);
        }
    }
}

// ---------------------------------------------------------------------------
extern "C" void kernel_launch(void* const* d_in, const int* in_sizes, int n_in,
                              void* d_out, int out_size)
{
    const float* x  = (const float*)d_in[0];
    const float* gw = (const float*)d_in[1];
    const float* w1 = (const float*)d_in[2];
    const float* b1 = (const float*)d_in[3];
    const float* w2 = (const float*)d_in[4];
    const float* b2 = (const float*)d_in[5];
    float* out = (float*)d_out;

    router_kernel<<<NTOK / 8, 256>>>(x, gw);
    topk_kernel<<<NGRP, 256>>>();

    int n4 = out_size / 4;
    zero_kernel<<<(n4 + 255) / 256, 256>>>((float4*)out, n4);

    dim3 g1(DFFN / BN, KCAP / BM, NGRP);
    gemm1_tc<<<g1, 256>>>(x, w1, b1);

    dim3 g2(DD / BN, KCAP / BM, NGRP);
    gemm2_tc<<<g2, 256>>>(w2, b2, out);
}

// round 4
// speedup vs baseline: 3.0555x; 1.0765x over previous
#include <cuda_runtime.h>
#include <math.h>
#include <stdint.h>

// Problem constants
#define BB   8
#define SS   8192
#define DD   512
#define EE   16
#define DFFN 512
#define KCAP 1024            // S/E * CAPACITY
#define NTOK (BB*SS)         // 65536
#define NGRP (BB*EE)         // 128

// Scratch — referenced ONLY inside device code (host-side symbol use is UB)
__device__ float g_aff [NGRP * SS];
__device__ int   g_idx [NGRP * KCAP];
__device__ float g_gate[NGRP * KCAP];
__device__ float g_h   [(size_t)NGRP * KCAP * DFFN];     // 256MB, tf32-rounded
__device__ float g_xt  [(size_t)NTOK * DD];              // 128MB, x tf32-rounded
__device__ float g_w1t [(size_t)EE * DD * DFFN];         // 16MB
__device__ float g_w2t [(size_t)EE * DFFN * DD];         // 16MB

__device__ __forceinline__ unsigned f2tf32(float f)
{
    unsigned r;
    asm("cvt.rna.tf32.f32 %0, %1;" : "=r"(r) : "f"(f));
    return r;
}

__device__ __forceinline__ float4 round4(float4 v)
{
    float4 o;
    o.x = __uint_as_float(f2tf32(v.x));
    o.y = __uint_as_float(f2tf32(v.y));
    o.z = __uint_as_float(f2tf32(v.z));
    o.w = __uint_as_float(f2tf32(v.w));
    return o;
}

// ---------------------------------------------------------------------------
// Kernel 0a/0b/0c: tf32 pre-round into device-global scratch (dst in-kernel)
// ---------------------------------------------------------------------------
__global__ void cvt_x_kernel(const float4* __restrict__ src, int n4)
{
    int i = blockIdx.x * blockDim.x + threadIdx.x;
    if (i < n4) ((float4*)g_xt)[i] = round4(src[i]);
}
__global__ void cvt_w1_kernel(const float4* __restrict__ src, int n4)
{
    int i = blockIdx.x * blockDim.x + threadIdx.x;
    if (i < n4) ((float4*)g_w1t)[i] = round4(src[i]);
}
__global__ void cvt_w2_kernel(const float4* __restrict__ src, int n4)
{
    int i = blockIdx.x * blockDim.x + threadIdx.x;
    if (i < n4) ((float4*)g_w2t)[i] = round4(src[i]);
}

// ---------------------------------------------------------------------------
// Kernel 1: router (unchanged)
// ---------------------------------------------------------------------------
__global__ __launch_bounds__(256) void router_kernel(
    const float* __restrict__ x, const float* __restrict__ gw)
{
    __shared__ float sgw[EE * DD];
    for (int i = threadIdx.x; i < EE * DD; i += blockDim.x) {
        int e = i / DD, d = i - e * DD;
        sgw[i] = gw[d * EE + e];
    }
    __syncthreads();

    int warp = threadIdx.x >> 5, lane = threadIdx.x & 31;
    int t = blockIdx.x * 8 + warp;
    const float* xr = x + (size_t)t * DD;

    float acc[EE];
#pragma unroll
    for (int e = 0; e < EE; e++) acc[e] = 0.f;
#pragma unroll
    for (int i = 0; i < DD / 32; i++) {
        int d = lane + 32 * i;
        float xv = xr[d];
#pragma unroll
        for (int e = 0; e < EE; e++)
            acc[e] = fmaf(xv, sgw[e * DD + d], acc[e]);
    }
#pragma unroll
    for (int e = 0; e < EE; e++) {
#pragma unroll
        for (int o = 16; o > 0; o >>= 1)
            acc[e] += __shfl_xor_sync(0xffffffffu, acc[e], o);
    }
    float m = acc[0];
#pragma unroll
    for (int e = 1; e < EE; e++) m = fmaxf(m, acc[e]);
    float s = 0.f;
#pragma unroll
    for (int e = 0; e < EE; e++) { acc[e] = expf(acc[e] - m); s += acc[e]; }
    float inv = 1.f / s;

    int b = t / SS, srow = t - b * SS;
    if (lane < EE)
        g_aff[((size_t)(b * EE + lane)) * SS + srow] = acc[lane] * inv;
}

// ---------------------------------------------------------------------------
// Kernel 2: exact radix-select top-KCAP (unchanged)
// ---------------------------------------------------------------------------
__global__ __launch_bounds__(256) void topk_kernel()
{
    int g = blockIdx.x;
    const float* a = g_aff + (size_t)g * SS;
    int tid = threadIdx.x;

    __shared__ unsigned hist[256];
    __shared__ unsigned sPrefix, sMask, sRemain;

    if (tid == 0) { sPrefix = 0u; sMask = 0u; sRemain = KCAP; }
    __syncthreads();

    for (int pass = 3; pass >= 0; pass--) {
        for (int i = tid; i < 256; i += blockDim.x) hist[i] = 0u;
        __syncthreads();
        unsigned pfx = sPrefix, msk = sMask;
        int sh = pass * 8;
        for (int s = tid; s < SS; s += blockDim.x) {
            unsigned key = __float_as_uint(a[s]);
            if ((key & msk) == pfx)
                atomicAdd(&hist[(key >> sh) & 0xFFu], 1u);
        }
        __syncthreads();
        if (tid == 0) {
            unsigned need = sRemain, cum = 0;
            int d = 255;
            for (; d > 0; d--) {
                if (cum + hist[d] >= need) break;
                cum += hist[d];
            }
            sRemain = need - cum;
            sPrefix = pfx | ((unsigned)d << sh);
            sMask   = msk | (0xFFu << sh);
        }
        __syncthreads();
    }

    unsigned T = sPrefix;
    int kEq   = (int)sRemain;
    int cntGt = KCAP - kEq;

    __shared__ unsigned gtCnt;
    __shared__ int eqBase;
    __shared__ int warpEq[8];
    if (tid == 0) { gtCnt = 0u; eqBase = 0; }
    __syncthreads();

    int lane = tid & 31, warp = tid >> 5;
    int*   oIdx  = g_idx  + g * KCAP;
    float* oGate = g_gate + g * KCAP;

    for (int c = 0; c < SS / 256; c++) {
        int s = c * 256 + tid;
        float v = a[s];
        unsigned key = __float_as_uint(v);
        bool isGt = key > T, isEq = key == T;

        if (isGt) {
            unsigned p = atomicAdd(&gtCnt, 1u);
            oIdx[p] = s; oGate[p] = v;
        }
        unsigned bal = __ballot_sync(0xffffffffu, isEq);
        if (lane == 0) warpEq[warp] = __popc(bal);
        __syncthreads();
        if (isEq) {
            int r = eqBase;
#pragma unroll
            for (int w = 0; w < 8; w++) if (w < warp) r += warpEq[w];
            r += __popc(bal & ((1u << lane) - 1u));
            if (r < kEq) { oIdx[cntGt + r] = s; oGate[cntGt + r] = v; }
        }
        __syncthreads();
        if (tid == 0) {
            int tot = 0;
#pragma unroll
            for (int w = 0; w < 8; w++) tot += warpEq[w];
            eqBase += tot;
        }
        __syncthreads();
    }
}

// ---------------------------------------------------------------------------
// Kernel 3: zero the output
// ---------------------------------------------------------------------------
__global__ void zero_kernel(float4* __restrict__ out, int n4)
{
    int i = blockIdx.x * blockDim.x + threadIdx.x;
    if (i < n4) out[i] = make_float4(0.f, 0.f, 0.f, 0.f);
}

// ---------------------------------------------------------------------------
// TF32 tensor-core GEMM machinery (operands pre-rounded; no cvt in mainloop)
// Block tile 128x128x16, 256 threads = 8 warps (4 m x 2 n), warp tile 32x64.
// ---------------------------------------------------------------------------
#define BM 128
#define BN 128
#define BKT 16
#define LDA 20
#define LDB 136

__device__ __forceinline__ void cpa16(void* dst, const void* src)
{
    unsigned d = (unsigned)__cvta_generic_to_shared(dst);
    asm volatile("cp.async.cg.shared.global [%0], [%1], 16;\n" :: "r"(d), "l"(src));
}
#define CP_COMMIT() asm volatile("cp.async.commit_group;\n" ::: "memory")
#define CP_WAIT0()  asm volatile("cp.async.wait_group 0;\n" ::: "memory")

__device__ __forceinline__ void mma_tf32(float* c, const unsigned* a, const unsigned* b)
{
    asm volatile(
        "mma.sync.aligned.m16n8k8.row.col.f32.tf32.tf32.f32 "
        "{%0,%1,%2,%3}, {%4,%5,%6,%7}, {%8,%9}, {%0,%1,%2,%3};\n"
        : "+f"(c[0]), "+f"(c[1]), "+f"(c[2]), "+f"(c[3])
        : "r"(a[0]), "r"(a[1]), "r"(a[2]), "r"(a[3]), "r"(b[0]), "r"(b[1]));
}

__device__ __forceinline__ float gelu_tanh(float v)
{
    float v3 = v * v * v;
    float t = tanhf(0.7978845608028654f * (v + 0.044715f * v3));
    return 0.5f * v * (1.f + t);
}

// Core compute over one smem stage — raw bit loads, no conversion.
__device__ __forceinline__ void compute_stage(
    const unsigned* __restrict__ A, const unsigned* __restrict__ Bsh,
    int wm, int wn, int grp, int thr, float acc[2][8][4])
{
#pragma unroll
    for (int s = 0; s < 2; s++) {
        unsigned af[2][4], bf[8][2];
        int kc = s * 8 + thr;
#pragma unroll
        for (int f = 0; f < 2; f++) {
            int r0 = (wm * 32 + f * 16 + grp) * LDA;
            af[f][0] = A[r0 + kc];
            af[f][1] = A[r0 + 8 * LDA + kc];
            af[f][2] = A[r0 + kc + 4];
            af[f][3] = A[r0 + 8 * LDA + kc + 4];
        }
#pragma unroll
        for (int j = 0; j < 8; j++) {
            int col = wn * 64 + j * 8 + grp;
            bf[j][0] = Bsh[(s * 8 + thr) * LDB + col];
            bf[j][1] = Bsh[(s * 8 + 4 + thr) * LDB + col];
        }
#pragma unroll
        for (int f = 0; f < 2; f++)
#pragma unroll
            for (int j = 0; j < 8; j++)
                mma_tf32(acc[f][j], af[f], bf[j]);
    }
}

// ---------------------------------------------------------------------------
// Kernel 4: GEMM1 (TF32 TC) — fused gather + bias + gelu, stores tf32-rounded
// ---------------------------------------------------------------------------
__global__ __launch_bounds__(256) void gemm1_tc(
    const float* __restrict__ b1)
{
    __shared__ float As[2][BM * LDA];
    __shared__ float Bs[2][BKT * LDB];

    int g = blockIdx.z;
    int b = g >> 4, e = g & 15;
    int m0 = blockIdx.y * BM, n0 = blockIdx.x * BN;
    int tid = threadIdx.x;

    int mA0 = tid >> 2, kqA = (tid & 3) * 4;
    int mA1 = mA0 + 64;
    const float* xb = g_xt + (size_t)b * SS * DD;
    int rA0 = g_idx[g * KCAP + m0 + mA0];
    int rA1 = g_idx[g * KCAP + m0 + mA1];
    const float* srcA0 = xb + (size_t)rA0 * DD + kqA;
    const float* srcA1 = xb + (size_t)rA1 * DD + kqA;

    int kB0 = tid >> 5, nB = (tid & 31) * 4;
    int kB1 = kB0 + 8;
    const float* srcB = g_w1t + (size_t)e * DD * DFFN + n0 + nB;

    float acc[2][8][4] = {};

    int lane = tid & 31, warp = tid >> 5;
    int wm = warp >> 1, wn = warp & 1;
    int grp = lane >> 2, thr = lane & 3;

    {
        cpa16(&As[0][mA0 * LDA + kqA], srcA0);
        cpa16(&As[0][mA1 * LDA + kqA], srcA1);
        cpa16(&Bs[0][kB0 * LDB + nB], srcB + (size_t)kB0 * DFFN);
        cpa16(&Bs[0][kB1 * LDB + nB], srcB + (size_t)kB1 * DFFN);
        CP_COMMIT();
    }

    const int KT = DD / BKT;   // 32
    for (int kt = 0; kt < KT; kt++) {
        CP_WAIT0();
        __syncthreads();
        if (kt + 1 < KT) {
            int st = (kt + 1) & 1;
            int k0 = (kt + 1) * BKT;
            cpa16(&As[st][mA0 * LDA + kqA], srcA0 + k0);
            cpa16(&As[st][mA1 * LDA + kqA], srcA1 + k0);
            cpa16(&Bs[st][kB0 * LDB + nB], srcB + (size_t)(k0 + kB0) * DFFN);
            cpa16(&Bs[st][kB1 * LDB + nB], srcB + (size_t)(k0 + kB1) * DFFN);
            CP_COMMIT();
        }
        compute_stage((const unsigned*)As[kt & 1], (const unsigned*)Bs[kt & 1],
                      wm, wn, grp, thr, acc);
    }

    // Epilogue: bias + gelu -> g_h (stored tf32-rounded for gemm2's A path)
    float* Hrow = g_h + ((size_t)g * KCAP + m0) * DFFN + n0;
    const float* bias = b1 + e * DFFN + n0;
#pragma unroll
    for (int f = 0; f < 2; f++) {
        int mloc = wm * 32 + f * 16 + grp;
#pragma unroll
        for (int j = 0; j < 8; j++) {
            int nloc = wn * 64 + j * 8 + thr * 2;
            float bv0 = bias[nloc], bv1 = bias[nloc + 1];
            float2 v0, v1;
            v0.x = __uint_as_float(f2tf32(gelu_tanh(acc[f][j][0] + bv0)));
            v0.y = __uint_as_float(f2tf32(gelu_tanh(acc[f][j][1] + bv1)));
            *(float2*)&Hrow[(size_t)mloc * DFFN + nloc] = v0;
            v1.x = __uint_as_float(f2tf32(gelu_tanh(acc[f][j][2] + bv0)));
            v1.y = __uint_as_float(f2tf32(gelu_tanh(acc[f][j][3] + bv1)));
            *(float2*)&Hrow[(size_t)(mloc + 8) * DFFN + nloc] = v1;
        }
    }
}

// ---------------------------------------------------------------------------
// Kernel 5: GEMM2 (TF32 TC) — fused bias + gate + atomic scatter
// ---------------------------------------------------------------------------
__global__ __launch_bounds__(256) void gemm2_tc(
    const float* __restrict__ b2, float* __restrict__ out)
{
    __shared__ float As[2][BM * LDA];
    __shared__ float Bs[2][BKT * LDB];

    int g = blockIdx.z;
    int b = g >> 4, e = g & 15;
    int m0 = blockIdx.y * BM, n0 = blockIdx.x * BN;
    int tid = threadIdx.x;

    int mA0 = tid >> 2, kqA = (tid & 3) * 4;
    int mA1 = mA0 + 64;
    const float* srcA0 = g_h + ((size_t)(g * KCAP + m0 + mA0)) * DFFN + kqA;
    const float* srcA1 = g_h + ((size_t)(g * KCAP + m0 + mA1)) * DFFN + kqA;

    int kB0 = tid >> 5, nB = (tid & 31) * 4;
    int kB1 = kB0 + 8;
    const float* srcB = g_w2t + (size_t)e * DFFN * DD + n0 + nB;

    float acc[2][8][4] = {};

    int lane = tid & 31, warp = tid >> 5;
    int wm = warp >> 1, wn = warp & 1;
    int grp = lane >> 2, thr = lane & 3;

    {
        cpa16(&As[0][mA0 * LDA + kqA], srcA0);
        cpa16(&As[0][mA1 * LDA + kqA], srcA1);
        cpa16(&Bs[0][kB0 * LDB + nB], srcB + (size_t)kB0 * DD);
        cpa16(&Bs[0][kB1 * LDB + nB], srcB + (size_t)kB1 * DD);
        CP_COMMIT();
    }

    const int KT = DFFN / BKT;   // 32
    for (int kt = 0; kt < KT; kt++) {
        CP_WAIT0();
        __syncthreads();
        if (kt + 1 < KT) {
            int st = (kt + 1) & 1;
            int k0 = (kt + 1) * BKT;
            cpa16(&As[st][mA0 * LDA + kqA], srcA0 + k0);
            cpa16(&As[st][mA1 * LDA + kqA], srcA1 + k0);
            cpa16(&Bs[st][kB0 * LDB + nB], srcB + (size_t)(k0 + kB0) * DD);
            cpa16(&Bs[st][kB1 * LDB + nB], srcB + (size_t)(k0 + kB1) * DD);
            CP_COMMIT();
        }
        compute_stage((const unsigned*)As[kt & 1], (const unsigned*)Bs[kt & 1],
                      wm, wn, grp, thr, acc);
    }

    float* outB = out + (size_t)b * SS * DD;
    const float* bias = b2 + e * DD + n0;
#pragma unroll
    for (int f = 0; f < 2; f++) {
        int mloc = wm * 32 + f * 16 + grp;
        int gi = g * KCAP + m0 + mloc;
        int tok0 = g_idx[gi], tok1 = g_idx[gi + 8];
        float gt0 = g_gate[gi], gt1 = g_gate[gi + 8];
        float* o0 = outB + (size_t)tok0 * DD + n0;
        float* o1 = outB + (size_t)tok1 * DD + n0;
#pragma unroll
        for (int j = 0; j < 8; j++) {
            int nloc = wn * 64 + j * 8 + thr * 2;
            float bv0 = bias[nloc], bv1 = bias[nloc + 1];
            atomicAdd(&o0[nloc],     (acc[f][j][0] + bv0) * gt0);
            atomicAdd(&o0[nloc + 1], (acc[f][j][1] + bv1) * gt0);
            atomicAdd(&o1[nloc],     (acc[f][j][2] + bv0) * gt1);
            atomicAdd(&o1[nloc + 1], (acc[f][j][3] + bv1) * gt1);
        }
    }
}

// ---------------------------------------------------------------------------
extern "C" void kernel_launch(void* const* d_in, const int* in_sizes, int n_in,
                              void* d_out, int out_size)
{
    const float* x  = (const float*)d_in[0];
    const float* gw = (const float*)d_in[1];
    const float* w1 = (const float*)d_in[2];
    const float* b1 = (const float*)d_in[3];
    const float* w2 = (const float*)d_in[4];
    const float* b2 = (const float*)d_in[5];
    float* out = (float*)d_out;

    // Pre-round operands to tf32 (dst symbols referenced inside kernels)
    {
        int n4 = (NTOK * DD) / 4;
        cvt_x_kernel<<<(n4 + 255) / 256, 256>>>((const float4*)x, n4);
        int w4 = (EE * DD * DFFN) / 4;
        cvt_w1_kernel<<<(w4 + 255) / 256, 256>>>((const float4*)w1, w4);
        cvt_w2_kernel<<<(w4 + 255) / 256, 256>>>((const float4*)w2, w4);
    }

    router_kernel<<<NTOK / 8, 256>>>(x, gw);
    topk_kernel<<<NGRP, 256>>>();

    int n4 = out_size / 4;
    zero_kernel<<<(n4 + 255) / 256, 256>>>((float4*)out, n4);

    dim3 g1(DFFN / BN, KCAP / BM, NGRP);
    gemm1_tc<<<g1, 256>>>(b1);

    dim3 g2(DD / BN, KCAP / BM, NGRP);
    gemm2_tc<<<g2, 256>>>(b2, out);
}

// round 5
// speedup vs baseline: 3.2202x; 1.0539x over previous
#include <cuda_runtime.h>
#include <math.h>
#include <stdint.h>

// Problem constants
#define BB   8
#define SS   8192
#define DD   512
#define EE   16
#define DFFN 512
#define KCAP 1024            // S/E * CAPACITY
#define NTOK (BB*SS)         // 65536
#define NGRP (BB*EE)         // 128

// Scratch — referenced ONLY inside device code
__device__ float g_aff [NGRP * SS];
__device__ int   g_idx [NGRP * KCAP];
__device__ float g_gate[NGRP * KCAP];
__device__ float g_h   [(size_t)NGRP * KCAP * DFFN];     // 256MB, tf32-rounded
__device__ float g_xt  [(size_t)NTOK * DD];              // 128MB, x tf32-rounded
__device__ float g_w1t [(size_t)EE * DD * DFFN];         // 16MB
__device__ float g_w2t [(size_t)EE * DFFN * DD];         // 16MB

__device__ __forceinline__ unsigned f2tf32(float f)
{
    unsigned r;
    asm("cvt.rna.tf32.f32 %0, %1;" : "=r"(r) : "f"(f));
    return r;
}

__device__ __forceinline__ float4 round4(float4 v)
{
    float4 o;
    o.x = __uint_as_float(f2tf32(v.x));
    o.y = __uint_as_float(f2tf32(v.y));
    o.z = __uint_as_float(f2tf32(v.z));
    o.w = __uint_as_float(f2tf32(v.w));
    return o;
}

// ---------------------------------------------------------------------------
// Kernel 0b/0c: tf32 pre-round of weights
// ---------------------------------------------------------------------------
__global__ void cvt_w1_kernel(const float4* __restrict__ src, int n4)
{
    int i = blockIdx.x * blockDim.x + threadIdx.x;
    if (i < n4) ((float4*)g_w1t)[i] = round4(src[i]);
}
__global__ void cvt_w2_kernel(const float4* __restrict__ src, int n4)
{
    int i = blockIdx.x * blockDim.x + threadIdx.x;
    if (i < n4) ((float4*)g_w2t)[i] = round4(src[i]);
}

// ---------------------------------------------------------------------------
// Kernel 1: router v2 — 4 tokens/warp, float4 smem gw, fused softmax and
// fused x->tf32 conversion (writes g_xt). Logits stay exact fp32.
// ---------------------------------------------------------------------------
__global__ __launch_bounds__(256) void router2_kernel(
    const float4* __restrict__ x4, const float* __restrict__ gw)
{
    __shared__ float4 sgw4[EE][DD / 4];   // [e][dq] : conflict-free LDS.128
    int tid = threadIdx.x;
    for (int i = tid; i < EE * (DD / 4); i += 256) {
        int e = i >> 7, dq = i & 127;
        float4 v;
        v.x = gw[(4 * dq + 0) * EE + e];
        v.y = gw[(4 * dq + 1) * EE + e];
        v.z = gw[(4 * dq + 2) * EE + e];
        v.w = gw[(4 * dq + 3) * EE + e];
        sgw4[e][dq] = v;
    }
    __syncthreads();

    int warp = tid >> 5, lane = tid & 31;
    int t0 = blockIdx.x * 32 + warp * 4;      // 4 tokens per warp
    int b = t0 / SS;                          // 32-token block never crosses b

    float acc[4][EE];
#pragma unroll
    for (int tt = 0; tt < 4; tt++)
#pragma unroll
        for (int e = 0; e < EE; e++) acc[tt][e] = 0.f;

#pragma unroll
    for (int q = 0; q < 4; q++) {
        int dq = lane + q * 32;
        float4 xv[4];
#pragma unroll
        for (int tt = 0; tt < 4; tt++)
            xv[tt] = x4[(size_t)(t0 + tt) * (DD / 4) + dq];
        // fused tf32 conversion of x
#pragma unroll
        for (int tt = 0; tt < 4; tt++)
            ((float4*)g_xt)[(size_t)(t0 + tt) * (DD / 4) + dq] = round4(xv[tt]);
#pragma unroll
        for (int e = 0; e < EE; e++) {
            float4 w = sgw4[e][dq];
#pragma unroll
            for (int tt = 0; tt < 4; tt++) {
                acc[tt][e] = fmaf(xv[tt].x, w.x, acc[tt][e]);
                acc[tt][e] = fmaf(xv[tt].y, w.y, acc[tt][e]);
                acc[tt][e] = fmaf(xv[tt].z, w.z, acc[tt][e]);
                acc[tt][e] = fmaf(xv[tt].w, w.w, acc[tt][e]);
            }
        }
    }

    // reduce partials across the warp (every lane ends with full sums)
#pragma unroll
    for (int tt = 0; tt < 4; tt++)
#pragma unroll
        for (int e = 0; e < EE; e++)
#pragma unroll
            for (int o = 16; o > 0; o >>= 1)
                acc[tt][e] += __shfl_xor_sync(0xffffffffu, acc[tt][e], o);

    // softmax per token; lane e<16 computes exp for its expert, sums via shfl
    int le = lane & 15;
#pragma unroll
    for (int tt = 0; tt < 4; tt++) {
        float m = acc[tt][0];
#pragma unroll
        for (int e = 1; e < EE; e++) m = fmaxf(m, acc[tt][e]);
        float v = expf(acc[tt][le] - m);
        float s = v;
#pragma unroll
        for (int o = 8; o > 0; o >>= 1)
            s += __shfl_xor_sync(0xffffffffu, s, o);
        if (lane < EE) {
            int srow = t0 + tt - b * SS;
            g_aff[((size_t)(b * EE + lane)) * SS + srow] = v * (1.f / s);
        }
    }
}

// ---------------------------------------------------------------------------
// Kernel 2: exact radix-select top-KCAP (unchanged)
// ---------------------------------------------------------------------------
__global__ __launch_bounds__(256) void topk_kernel()
{
    int g = blockIdx.x;
    const float* a = g_aff + (size_t)g * SS;
    int tid = threadIdx.x;

    __shared__ unsigned hist[256];
    __shared__ unsigned sPrefix, sMask, sRemain;

    if (tid == 0) { sPrefix = 0u; sMask = 0u; sRemain = KCAP; }
    __syncthreads();

    for (int pass = 3; pass >= 0; pass--) {
        for (int i = tid; i < 256; i += blockDim.x) hist[i] = 0u;
        __syncthreads();
        unsigned pfx = sPrefix, msk = sMask;
        int sh = pass * 8;
        for (int s = tid; s < SS; s += blockDim.x) {
            unsigned key = __float_as_uint(a[s]);
            if ((key & msk) == pfx)
                atomicAdd(&hist[(key >> sh) & 0xFFu], 1u);
        }
        __syncthreads();
        if (tid == 0) {
            unsigned need = sRemain, cum = 0;
            int d = 255;
            for (; d > 0; d--) {
                if (cum + hist[d] >= need) break;
                cum += hist[d];
            }
            sRemain = need - cum;
            sPrefix = pfx | ((unsigned)d << sh);
            sMask   = msk | (0xFFu << sh);
        }
        __syncthreads();
    }

    unsigned T = sPrefix;
    int kEq   = (int)sRemain;
    int cntGt = KCAP - kEq;

    __shared__ unsigned gtCnt;
    __shared__ int eqBase;
    __shared__ int warpEq[8];
    if (tid == 0) { gtCnt = 0u; eqBase = 0; }
    __syncthreads();

    int lane = tid & 31, warp = tid >> 5;
    int*   oIdx  = g_idx  + g * KCAP;
    float* oGate = g_gate + g * KCAP;

    for (int c = 0; c < SS / 256; c++) {
        int s = c * 256 + tid;
        float v = a[s];
        unsigned key = __float_as_uint(v);
        bool isGt = key > T, isEq = key == T;

        if (isGt) {
            unsigned p = atomicAdd(&gtCnt, 1u);
            oIdx[p] = s; oGate[p] = v;
        }
        unsigned bal = __ballot_sync(0xffffffffu, isEq);
        if (lane == 0) warpEq[warp] = __popc(bal);
        __syncthreads();
        if (isEq) {
            int r = eqBase;
#pragma unroll
            for (int w = 0; w < 8; w++) if (w < warp) r += warpEq[w];
            r += __popc(bal & ((1u << lane) - 1u));
            if (r < kEq) { oIdx[cntGt + r] = s; oGate[cntGt + r] = v; }
        }
        __syncthreads();
        if (tid == 0) {
            int tot = 0;
#pragma unroll
            for (int w = 0; w < 8; w++) tot += warpEq[w];
            eqBase += tot;
        }
        __syncthreads();
    }
}

// ---------------------------------------------------------------------------
// Kernel 3: zero the output
// ---------------------------------------------------------------------------
__global__ void zero_kernel(float4* __restrict__ out, int n4)
{
    int i = blockIdx.x * blockDim.x + threadIdx.x;
    if (i < n4) out[i] = make_float4(0.f, 0.f, 0.f, 0.f);
}

// ---------------------------------------------------------------------------
// TF32 tensor-core GEMM machinery (operands pre-rounded; no cvt in mainloop)
// ---------------------------------------------------------------------------
#define BM 128
#define BN 128
#define BKT 16
#define LDA 20
#define LDB 136

__device__ __forceinline__ void cpa16(void* dst, const void* src)
{
    unsigned d = (unsigned)__cvta_generic_to_shared(dst);
    asm volatile("cp.async.cg.shared.global [%0], [%1], 16;\n" :: "r"(d), "l"(src));
}
#define CP_COMMIT() asm volatile("cp.async.commit_group;\n" ::: "memory")
#define CP_WAIT0()  asm volatile("cp.async.wait_group 0;\n" ::: "memory")

__device__ __forceinline__ void mma_tf32(float* c, const unsigned* a, const unsigned* b)
{
    asm volatile(
        "mma.sync.aligned.m16n8k8.row.col.f32.tf32.tf32.f32 "
        "{%0,%1,%2,%3}, {%4,%5,%6,%7}, {%8,%9}, {%0,%1,%2,%3};\n"
        : "+f"(c[0]), "+f"(c[1]), "+f"(c[2]), "+f"(c[3])
        : "r"(a[0]), "r"(a[1]), "r"(a[2]), "r"(a[3]), "r"(b[0]), "r"(b[1]));
}

__device__ __forceinline__ float gelu_tanh(float v)
{
    float v3 = v * v * v;
    float t = tanhf(0.7978845608028654f * (v + 0.044715f * v3));
    return 0.5f * v * (1.f + t);
}

__device__ __forceinline__ void compute_stage(
    const unsigned* __restrict__ A, const unsigned* __restrict__ Bsh,
    int wm, int wn, int grp, int thr, float acc[2][8][4])
{
#pragma unroll
    for (int s = 0; s < 2; s++) {
        unsigned af[2][4], bf[8][2];
        int kc = s * 8 + thr;
#pragma unroll
        for (int f = 0; f < 2; f++) {
            int r0 = (wm * 32 + f * 16 + grp) * LDA;
            af[f][0] = A[r0 + kc];
            af[f][1] = A[r0 + 8 * LDA + kc];
            af[f][2] = A[r0 + kc + 4];
            af[f][3] = A[r0 + 8 * LDA + kc + 4];
        }
#pragma unroll
        for (int j = 0; j < 8; j++) {
            int col = wn * 64 + j * 8 + grp;
            bf[j][0] = Bsh[(s * 8 + thr) * LDB + col];
            bf[j][1] = Bsh[(s * 8 + 4 + thr) * LDB + col];
        }
#pragma unroll
        for (int f = 0; f < 2; f++)
#pragma unroll
            for (int j = 0; j < 8; j++)
                mma_tf32(acc[f][j], af[f], bf[j]);
    }
}

// ---------------------------------------------------------------------------
// Kernel 4: GEMM1 (TF32 TC) — fused gather + bias + gelu, stores tf32-rounded
// ---------------------------------------------------------------------------
__global__ __launch_bounds__(256) void gemm1_tc(
    const float* __restrict__ b1)
{
    __shared__ float As[2][BM * LDA];
    __shared__ float Bs[2][BKT * LDB];

    int g = blockIdx.z;
    int b = g >> 4, e = g & 15;
    int m0 = blockIdx.y * BM, n0 = blockIdx.x * BN;
    int tid = threadIdx.x;

    int mA0 = tid >> 2, kqA = (tid & 3) * 4;
    int mA1 = mA0 + 64;
    const float* xb = g_xt + (size_t)b * SS * DD;
    int rA0 = g_idx[g * KCAP + m0 + mA0];
    int rA1 = g_idx[g * KCAP + m0 + mA1];
    const float* srcA0 = xb + (size_t)rA0 * DD + kqA;
    const float* srcA1 = xb + (size_t)rA1 * DD + kqA;

    int kB0 = tid >> 5, nB = (tid & 31) * 4;
    int kB1 = kB0 + 8;
    const float* srcB = g_w1t + (size_t)e * DD * DFFN + n0 + nB;

    float acc[2][8][4] = {};

    int lane = tid & 31, warp = tid >> 5;
    int wm = warp >> 1, wn = warp & 1;
    int grp = lane >> 2, thr = lane & 3;

    {
        cpa16(&As[0][mA0 * LDA + kqA], srcA0);
        cpa16(&As[0][mA1 * LDA + kqA], srcA1);
        cpa16(&Bs[0][kB0 * LDB + nB], srcB + (size_t)kB0 * DFFN);
        cpa16(&Bs[0][kB1 * LDB + nB], srcB + (size_t)kB1 * DFFN);
        CP_COMMIT();
    }

    const int KT = DD / BKT;   // 32
    for (int kt = 0; kt < KT; kt++) {
        CP_WAIT0();
        __syncthreads();
        if (kt + 1 < KT) {
            int st = (kt + 1) & 1;
            int k0 = (kt + 1) * BKT;
            cpa16(&As[st][mA0 * LDA + kqA], srcA0 + k0);
            cpa16(&As[st][mA1 * LDA + kqA], srcA1 + k0);
            cpa16(&Bs[st][kB0 * LDB + nB], srcB + (size_t)(k0 + kB0) * DFFN);
            cpa16(&Bs[st][kB1 * LDB + nB], srcB + (size_t)(k0 + kB1) * DFFN);
            CP_COMMIT();
        }
        compute_stage((const unsigned*)As[kt & 1], (const unsigned*)Bs[kt & 1],
                      wm, wn, grp, thr, acc);
    }

    float* Hrow = g_h + ((size_t)g * KCAP + m0) * DFFN + n0;
    const float* bias = b1 + e * DFFN + n0;
#pragma unroll
    for (int f = 0; f < 2; f++) {
        int mloc = wm * 32 + f * 16 + grp;
#pragma unroll
        for (int j = 0; j < 8; j++) {
            int nloc = wn * 64 + j * 8 + thr * 2;
            float bv0 = bias[nloc], bv1 = bias[nloc + 1];
            float2 v0, v1;
            v0.x = __uint_as_float(f2tf32(gelu_tanh(acc[f][j][0] + bv0)));
            v0.y = __uint_as_float(f2tf32(gelu_tanh(acc[f][j][1] + bv1)));
            *(float2*)&Hrow[(size_t)mloc * DFFN + nloc] = v0;
            v1.x = __uint_as_float(f2tf32(gelu_tanh(acc[f][j][2] + bv0)));
            v1.y = __uint_as_float(f2tf32(gelu_tanh(acc[f][j][3] + bv1)));
            *(float2*)&Hrow[(size_t)(mloc + 8) * DFFN + nloc] = v1;
        }
    }
}

// ---------------------------------------------------------------------------
// Kernel 5: GEMM2 (TF32 TC) — fused bias + gate + atomic scatter
// ---------------------------------------------------------------------------
__global__ __launch_bounds__(256) void gemm2_tc(
    const float* __restrict__ b2, float* __restrict__ out)
{
    __shared__ float As[2][BM * LDA];
    __shared__ float Bs[2][BKT * LDB];

    int g = blockIdx.z;
    int b = g >> 4, e = g & 15;
    int m0 = blockIdx.y * BM, n0 = blockIdx.x * BN;
    int tid = threadIdx.x;

    int mA0 = tid >> 2, kqA = (tid & 3) * 4;
    int mA1 = mA0 + 64;
    const float* srcA0 = g_h + ((size_t)(g * KCAP + m0 + mA0)) * DFFN + kqA;
    const float* srcA1 = g_h + ((size_t)(g * KCAP + m0 + mA1)) * DFFN + kqA;

    int kB0 = tid >> 5, nB = (tid & 31) * 4;
    int kB1 = kB0 + 8;
    const float* srcB = g_w2t + (size_t)e * DFFN * DD + n0 + nB;

    float acc[2][8][4] = {};

    int lane = tid & 31, warp = tid >> 5;
    int wm = warp >> 1, wn = warp & 1;
    int grp = lane >> 2, thr = lane & 3;

    {
        cpa16(&As[0][mA0 * LDA + kqA], srcA0);
        cpa16(&As[0][mA1 * LDA + kqA], srcA1);
        cpa16(&Bs[0][kB0 * LDB + nB], srcB + (size_t)kB0 * DD);
        cpa16(&Bs[0][kB1 * LDB + nB], srcB + (size_t)kB1 * DD);
        CP_COMMIT();
    }

    const int KT = DFFN / BKT;   // 32
    for (int kt = 0; kt < KT; kt++) {
        CP_WAIT0();
        __syncthreads();
        if (kt + 1 < KT) {
            int st = (kt + 1) & 1;
            int k0 = (kt + 1) * BKT;
            cpa16(&As[st][mA0 * LDA + kqA], srcA0 + k0);
            cpa16(&As[st][mA1 * LDA + kqA], srcA1 + k0);
            cpa16(&Bs[st][kB0 * LDB + nB], srcB + (size_t)(k0 + kB0) * DD);
            cpa16(&Bs[st][kB1 * LDB + nB], srcB + (size_t)(k0 + kB1) * DD);
            CP_COMMIT();
        }
        compute_stage((const unsigned*)As[kt & 1], (const unsigned*)Bs[kt & 1],
                      wm, wn, grp, thr, acc);
    }

    float* outB = out + (size_t)b * SS * DD;
    const float* bias = b2 + e * DD + n0;
#pragma unroll
    for (int f = 0; f < 2; f++) {
        int mloc = wm * 32 + f * 16 + grp;
        int gi = g * KCAP + m0 + mloc;
        int tok0 = g_idx[gi], tok1 = g_idx[gi + 8];
        float gt0 = g_gate[gi], gt1 = g_gate[gi + 8];
        float* o0 = outB + (size_t)tok0 * DD + n0;
        float* o1 = outB + (size_t)tok1 * DD + n0;
#pragma unroll
        for (int j = 0; j < 8; j++) {
            int nloc = wn * 64 + j * 8 + thr * 2;
            float bv0 = bias[nloc], bv1 = bias[nloc + 1];
            atomicAdd(&o0[nloc],     (acc[f][j][0] + bv0) * gt0);
            atomicAdd(&o0[nloc + 1], (acc[f][j][1] + bv1) * gt0);
            atomicAdd(&o1[nloc],     (acc[f][j][2] + bv0) * gt1);
            atomicAdd(&o1[nloc + 1], (acc[f][j][3] + bv1) * gt1);
        }
    }
}

// ---------------------------------------------------------------------------
extern "C" void kernel_launch(void* const* d_in, const int* in_sizes, int n_in,
                              void* d_out, int out_size)
{
    const float* x  = (const float*)d_in[0];
    const float* gw = (const float*)d_in[1];
    const float* w1 = (const float*)d_in[2];
    const float* b1 = (const float*)d_in[3];
    const float* w2 = (const float*)d_in[4];
    const float* b2 = (const float*)d_in[5];
    float* out = (float*)d_out;

    // weight tf32 pre-round
    int w4 = (EE * DD * DFFN) / 4;
    cvt_w1_kernel<<<(w4 + 255) / 256, 256>>>((const float4*)w1, w4);
    cvt_w2_kernel<<<(w4 + 255) / 256, 256>>>((const float4*)w2, w4);

    // router (fp32 logits + softmax) + fused x->tf32
    router2_kernel<<<NTOK / 32, 256>>>((const float4*)x, gw);
    topk_kernel<<<NGRP, 256>>>();

    int n4 = out_size / 4;
    zero_kernel<<<(n4 + 255) / 256, 256>>>((float4*)out, n4);

    dim3 g1(DFFN / BN, KCAP / BM, NGRP);
    gemm1_tc<<<g1, 256>>>(b1);

    dim3 g2(DD / BN, KCAP / BM, NGRP);
    gemm2_tc<<<g2, 256>>>(b2, out);
}